// round 9
// baseline (speedup 1.0000x reference)
#include <cuda_runtime.h>
#include <cstdint>

// B=4096 poses x N=4096 points, pure HBM streaming reduction (201 MB).
// R9: TMA bulk-copy pipeline. 1024 CTAs x 128 thr; 4 INDEPENDENT warps per
// CTA, one pose each. Each warp: private smem ring (2 x 3 KB) + 2 mbarriers,
// 16 rounds of { wait full -> process 256 pts from smem -> refill via
// cp.async.bulk }. Load issue decoupled from compute: 1 bulk instr per 3 KB.

#define NPTS 4096
#define WPC 4                    // warps per CTA (independent poses)
#define BUF_BYTES 3072           // 256 points per buffer
#define ROUNDS 16                // 16 * 3072 B = one 48 KB row
#define RING 2

__device__ __forceinline__ uint32_t s2u(const void* p) {
    return (uint32_t)__cvta_generic_to_shared(p);
}
#define MBAR_INIT(a, c) \
    asm volatile("mbarrier.init.shared.b64 [%0], %1;" :: "r"(a), "r"(c) : "memory")
#define MBAR_EXPECT_TX(a, n) \
    asm volatile("mbarrier.arrive.expect_tx.shared.b64 _, [%0], %1;" :: "r"(a), "r"(n) : "memory")
#define FENCE_ASYNC() asm volatile("fence.proxy.async.shared::cta;" ::: "memory")
#define BULK_G2S(dst, src, sz, mb) \
    asm volatile("cp.async.bulk.shared::cluster.global.mbarrier::complete_tx::bytes " \
                 "[%0], [%1], %2, [%3];" \
                 :: "r"(dst), "l"(src), "r"(sz), "r"(mb) : "memory")

__device__ __forceinline__ void mbar_wait(uint32_t mbar, uint32_t parity) {
    asm volatile(
        "{\n\t.reg .pred P;\n\t"
        "WAIT_%=:\n\t"
        "mbarrier.try_wait.parity.acquire.cta.shared::cta.b64 P, [%0], %1, 0x989680;\n\t"
        "@P bra.uni DONE_%=;\n\t"
        "bra.uni WAIT_%=;\n\t"
        "DONE_%=:\n\t}"
        :: "r"(mbar), "r"(parity) : "memory");
}

__device__ __forceinline__ void process4(
    const float4 A, const float4 Bv, const float4 C,
    const float r00, const float r01, const float r02,
    const float r10, const float r11, const float r12,
    const float r20, const float r21, const float r22,
    const float trx, const float try_, const float trz,
    float& sum, int& cnt)
{
    // AABB bounds (identical double->float rounding to the numpy reference)
    const float lox = (float)(-0.001782 - (0.204416 / 2.0 + 0.001));
    const float hix = (float)(-0.001782 + (0.204416 / 2.0 + 0.001));
    const float loy = (float)(1.005e-05 - (0.0632517 / 2.0 + 0.001));
    const float hiy = (float)(1.005e-05 + (0.0632517 / 2.0 + 0.001));
    const float loz = (float)(0.0431621 - (0.1381738 / 2.0 + 0.001));
    const float hiz = (float)(0.0431621 + (0.1381738 / 2.0 + 0.001));

    const float px[4] = {A.x, A.w, Bv.z, C.y};
    const float py[4] = {A.y, Bv.x, Bv.w, C.z};
    const float pz[4] = {A.z, Bv.y, C.x, C.w};
#pragma unroll
    for (int k = 0; k < 4; ++k) {
        const float x = px[k], y = py[k], z = pz[k];
        const float rx = fmaf(r00, x, fmaf(r01, y, fmaf(r02, z, -trx)));
        const float ry = fmaf(r10, x, fmaf(r11, y, fmaf(r12, z, -try_)));
        const float rz = fmaf(r20, x, fmaf(r21, y, fmaf(r22, z, -trz)));
        const bool inside =
            (rx >= lox) & (rx <= hix) &
            (ry >= loy) & (ry <= hiy) &
            (rz >= loz) & (rz <= hiz);
        const float r2 = fmaf(rx, rx, fmaf(ry, ry, rz * rz));
        const float nrm = r2 * rsqrtf(fmaxf(r2, 1e-12f));  // = sqrt(r2)
        sum += inside ? nrm : 0.0f;
        cnt += (int)inside;
    }
}

__global__ __launch_bounds__(32 * WPC, 7) void collision_dist_kernel(
    const float* __restrict__ trans,   // [B,3]
    const float* __restrict__ quat,    // [B,4]
    const float* __restrict__ pc,      // [B,N,3]
    float* __restrict__ out)           // [B,1]
{
    __shared__ __align__(128) unsigned char sbuf[WPC * RING * BUF_BYTES];
    __shared__ __align__(8)  unsigned long long smbar[WPC * RING];

    const int tid  = threadIdx.x;
    const int warp = tid >> 5;
    const int lane = tid & 31;
    const int b    = blockIdx.x * WPC + warp;      // pose

    unsigned char* mybuf = sbuf + warp * RING * BUF_BYTES;
    const uint32_t mb0 = s2u(&smbar[warp * RING + 0]);
    const uint32_t mb1 = s2u(&smbar[warp * RING + 1]);
    const uint32_t sb0 = s2u(mybuf);
    const uint32_t sb1 = s2u(mybuf + BUF_BYTES);

    const char* gsrc = (const char*)pc + (size_t)b * (size_t)NPTS * 12;

    // ---- init warp-private mbarriers, kick off first two bulk copies ----
    if (lane == 0) {
        MBAR_INIT(mb0, 1);
        MBAR_INIT(mb1, 1);
        FENCE_ASYNC();
        MBAR_EXPECT_TX(mb0, BUF_BYTES);
        BULK_G2S(sb0, gsrc, BUF_BYTES, mb0);
        MBAR_EXPECT_TX(mb1, BUF_BYTES);
        BULK_G2S(sb1, gsrc + BUF_BYTES, BUF_BYTES, mb1);
    }
    __syncwarp();

    // ---- per-pose setup overlaps the first copies ----
    const float qx = __ldg(&quat[b * 4 + 0]);
    const float qy = __ldg(&quat[b * 4 + 1]);
    const float qz = __ldg(&quat[b * 4 + 2]);
    const float qw = __ldg(&quat[b * 4 + 3]);
    const float inv = 1.0f / (qx * qx + qy * qy + qz * qz + qw * qw);
    const float tx = -qx * inv, ty = -qy * inv, tz = -qz * inv, tw = qw * inv;

    const float txx = tx * tx, tyy = ty * ty, tzz = tz * tz, tww = tw * tw;
    const float r00 = tww + txx - tyy - tzz;
    const float r11 = tww - txx + tyy - tzz;
    const float r22 = tww - txx - tyy + tzz;
    const float r01 = 2.0f * (tx * ty - tw * tz);
    const float r02 = 2.0f * (tx * tz + tw * ty);
    const float r10 = 2.0f * (tx * ty + tw * tz);
    const float r12 = 2.0f * (ty * tz - tw * tx);
    const float r20 = 2.0f * (tx * tz - tw * ty);
    const float r21 = 2.0f * (ty * tz + tw * tx);

    const float trx  = __ldg(&trans[b * 3 + 0]);
    const float try_ = __ldg(&trans[b * 3 + 1]);
    const float trz  = __ldg(&trans[b * 3 + 2]);

    float sum = 0.0f;
    int   cnt = 0;
    int ph0 = 0, ph1 = 0;

#pragma unroll 2
    for (int r = 0; r < ROUNDS; ++r) {
        const int s = r & 1;
        const uint32_t mb = s ? mb1 : mb0;
        if (s) { mbar_wait(mb, ph1); ph1 ^= 1; }
        else   { mbar_wait(mb, ph0); ph0 ^= 1; }

        const unsigned char* bp = mybuf + s * BUF_BYTES;
        // 64 groups of 48 B; lane handles groups (lane) and (lane+32).
        // 48 B lane stride -> conflict-free LDS.128 (distinct banks per phase).
        const float4* g1 = reinterpret_cast<const float4*>(bp + lane * 48);
        const float4* g2 = reinterpret_cast<const float4*>(bp + (lane + 32) * 48);
        const float4 a0 = g1[0], a1 = g1[1], a2 = g1[2];
        const float4 c0 = g2[0], c1 = g2[1], c2 = g2[2];
        process4(a0, a1, a2, r00, r01, r02, r10, r11, r12, r20, r21, r22,
                 trx, try_, trz, sum, cnt);
        process4(c0, c1, c2, r00, r01, r02, r10, r11, r12, r20, r21, r22,
                 trx, try_, trz, sum, cnt);

        __syncwarp();                       // all lanes done reading buffer s
        if (lane == 0 && r + RING < ROUNDS) {
            FENCE_ASYNC();                  // order generic reads before async write
            MBAR_EXPECT_TX(mb, BUF_BYTES);
            BULK_G2S(s ? sb1 : sb0, gsrc + (size_t)(r + RING) * BUF_BYTES,
                     BUF_BYTES, mb);
        }
    }

    // ---- warp reduction (warps fully independent; no block sync) ----
#pragma unroll
    for (int off = 16; off > 0; off >>= 1) {
        sum += __shfl_down_sync(0xFFFFFFFFu, sum, off);
        cnt += __shfl_down_sync(0xFFFFFFFFu, cnt, off);
    }
    if (lane == 0) {
        const float dist = (cnt > 0) ? (-sum / (float)max(cnt, 1)) : 1.0f;
        out[b] = dist * 10000.0f;
    }
}

extern "C" void kernel_launch(void* const* d_in, const int* in_sizes, int n_in,
                              void* d_out, int out_size)
{
    const float* trans = (const float*)d_in[0];  // [4096,3]
    const float* quat  = (const float*)d_in[1];  // [4096,4]
    const float* pc    = (const float*)d_in[2];  // [4096,4096,3]
    float* out = (float*)d_out;                  // [4096,1]

    const int B = in_sizes[0] / 3;               // 4096 poses
    collision_dist_kernel<<<B / WPC, 32 * WPC>>>(trans, quat, pc, out);
}